// round 3
// baseline (speedup 1.0000x reference)
#include <cuda_runtime.h>
#include <math.h>

#define NN 4096          // D*W*H = 16*16*16
#define LL 21            // labels
#define LN (LL * NN)

// ---------------- device scratch (static allocation, allowed) ----------------
__device__ float g_K[16777216];   // 4096 x 4096 bilateral kernel, row-major (67 MB)
__device__ float g_F[NN * 8];     // per-voxel features: f0..f5, h=-0.5*|f|^2, pad
__device__ float g_q[LN];         // softmax output
__device__ float g_A[LN];         // spatial conv scratch / result
__device__ float g_B[LN];         // spatial conv scratch
__device__ float g_bi[LN];        // bilateral filter result (normalized)
__device__ float g_cur[LN];       // current logits between iterations
__device__ float g_Msp[LL * LL];  // compat @ spatial_weights
__device__ float g_Mbi[LL * LL];  // compat @ bilateral_weights
__device__ float g_G[16];         // 1D spatial Gaussian taps exp(-0.5 d^2)
__device__ float g_S[16];         // 1D normalizer sums S[a] = sum_t G[|a-t|]

// ---------------- tiny init kernels ----------------
__global__ void init_tables_k() {
    int t = threadIdx.x;
    if (t < 16) g_G[t] = expf(-0.5f * (float)(t * t));
    __syncwarp();
    if (t < 16) {
        float s = 0.f;
        for (int u = 0; u < 16; u++) {
            int d = t - u;
            s += expf(-0.5f * (float)(d * d));
        }
        g_S[t] = s;
    }
}

__global__ void feat_k(const float* __restrict__ img) {
    int n = blockIdx.x * 256 + threadIdx.x;
    if (n >= NN) return;
    float z = (float)(n >> 8);
    float y = (float)((n >> 4) & 15);
    float x = (float)(n & 15);
    const float ia = 1.f / 67.f;  // 1/ALPHA
    const float ib = 1.f / 3.f;   // 1/BETA
    float f0 = z * ia, f1 = y * ia, f2 = x * ia;
    float f3 = img[n] * ib;
    float f4 = img[NN + n] * ib;
    float f5 = img[2 * NN + n] * ib;
    float h = -0.5f * (f0 * f0 + f1 * f1 + f2 * f2 + f3 * f3 + f4 * f4 + f5 * f5);
    float* p = g_F + n * 8;
    p[0] = f0; p[1] = f1; p[2] = f2; p[3] = f3; p[4] = f4; p[5] = f5; p[6] = h; p[7] = 0.f;
}

__global__ void small_mats_k(const float* __restrict__ wsp,
                             const float* __restrict__ wbi,
                             const float* __restrict__ comp) {
    int t = threadIdx.x;
    if (t >= LL * LL) return;
    int l = t / LL, m = t % LL;
    float s1 = 0.f, s2 = 0.f;
    for (int k = 0; k < LL; k++) {
        float c = comp[l * LL + k];
        s1 += c * wsp[k * LL + m];
        s2 += c * wbi[k * LL + m];
    }
    g_Msp[t] = s1;
    g_Mbi[t] = s2;
}

// ---------------- K_bi build: grid (32 j-tiles, 32 i-tiles), block 128 ----------------
// warp w handles i-subrange of 32 rows; each lane owns 4 consecutive j columns.
__global__ void buildK_k() {
    int j0 = blockIdx.x * 128;
    int i0 = blockIdx.y * 128;
    int w = threadIdx.x >> 5;
    int lane = threadIdx.x & 31;
    int jb = j0 + lane * 4;

    float fj[4][7];
#pragma unroll
    for (int s = 0; s < 4; s++) {
        const float4* fp = (const float4*)(g_F + (size_t)(jb + s) * 8);
        float4 a = fp[0];
        float4 b = fp[1];
        fj[s][0] = a.x; fj[s][1] = a.y; fj[s][2] = a.z; fj[s][3] = a.w;
        fj[s][4] = b.x; fj[s][5] = b.y; fj[s][6] = b.z;  // b.z = h_j
    }

    for (int ii = 0; ii < 32; ii++) {
        int i = i0 + w * 32 + ii;
        const float4* fp = (const float4*)(g_F + (size_t)i * 8);
        float4 a = fp[0];
        float4 b = fp[1];  // b.z = h_i
        float o[4];
#pragma unroll
        for (int s = 0; s < 4; s++) {
            float e = b.z + fj[s][6]
                    + a.x * fj[s][0] + a.y * fj[s][1] + a.z * fj[s][2]
                    + b.x * fj[s][4] + b.y * fj[s][5] + a.w * fj[s][3];
            o[s] = __expf(fminf(e, 0.f));
        }
        float4 v = make_float4(o[0], o[1], o[2], o[3]);
        *(float4*)(g_K + (size_t)i * NN + jb) = v;
    }
}

// ---------------- per-iteration kernels ----------------
__global__ void softmax_k(const float* __restrict__ cur) {
    int n = blockIdx.x * 256 + threadIdx.x;
    if (n >= NN) return;
    float v[LL];
    float m = -1e30f;
#pragma unroll
    for (int l = 0; l < LL; l++) {
        v[l] = cur[l * NN + n];
        m = fmaxf(m, v[l]);
    }
    float s = 0.f;
#pragma unroll
    for (int l = 0; l < LL; l++) {
        v[l] = __expf(v[l] - m);
        s += v[l];
    }
    float inv = 1.f / s;
#pragma unroll
    for (int l = 0; l < LL; l++) g_q[l * NN + n] = v[l] * inv;
}

// 1D Gaussian conv along one axis (sh = 0:x, 4:y, 8:z). grid 336x256 = LN threads.
__global__ void conv_x_k() {
    int idx = blockIdx.x * 256 + threadIdx.x;
    int c = idx & 15;
    int base = idx - c;
    float a = 0.f;
#pragma unroll
    for (int t = 0; t < 16; t++) {
        int d = c - t; d = d < 0 ? -d : d;
        a += g_G[d] * g_q[base + t];
    }
    g_A[idx] = a;
}
__global__ void conv_y_k() {
    int idx = blockIdx.x * 256 + threadIdx.x;
    int c = (idx >> 4) & 15;
    int base = idx - (c << 4);
    float a = 0.f;
#pragma unroll
    for (int t = 0; t < 16; t++) {
        int d = c - t; d = d < 0 ? -d : d;
        a += g_G[d] * g_B[base + (t << 4)];
    }
    g_A[idx] = a;
}
__global__ void conv_z_k() {
    int idx = blockIdx.x * 256 + threadIdx.x;
    int c = (idx >> 8) & 15;
    int base = idx - (c << 8);
    float a = 0.f;
#pragma unroll
    for (int t = 0; t < 16; t++) {
        int d = c - t; d = d < 0 ? -d : d;
        a += g_G[d] * g_A[base + (t << 8)];
    }
    g_B[idx] = a;
}

// Bilateral filter GEMM: out[l,j] = (sum_i q[l,i] * K[j,i]) / (sum_i K[j,i])
// One warp handles 2 rows j (K symmetric -> row access). 256 blocks x 256 threads.
__global__ void gemm_bi_k() {
    int gw = (blockIdx.x * blockDim.x + threadIdx.x) >> 5;  // 0..2047
    int lane = threadIdx.x & 31;
    int j0 = gw * 2;
    const float4* Ka = (const float4*)(g_K + (size_t)j0 * NN);
    const float4* Kb = (const float4*)(g_K + (size_t)(j0 + 1) * NN);
    const float4* Q = (const float4*)g_q;

    float a0[LL], a1[LL];
#pragma unroll
    for (int l = 0; l < LL; l++) { a0[l] = 0.f; a1[l] = 0.f; }
    float n0 = 0.f, n1 = 0.f;

#pragma unroll 2
    for (int c = 0; c < NN / 128; c++) {
        int idx = c * 32 + lane;
        float4 k0 = Ka[idx];
        float4 k1 = Kb[idx];
        n0 += (k0.x + k0.y) + (k0.z + k0.w);
        n1 += (k1.x + k1.y) + (k1.z + k1.w);
#pragma unroll
        for (int l = 0; l < LL; l++) {
            float4 q4 = Q[l * (NN / 4) + idx];
            a0[l] = fmaf(q4.w, k0.w, fmaf(q4.z, k0.z, fmaf(q4.y, k0.y, fmaf(q4.x, k0.x, a0[l]))));
            a1[l] = fmaf(q4.w, k1.w, fmaf(q4.z, k1.z, fmaf(q4.y, k1.y, fmaf(q4.x, k1.x, a1[l]))));
        }
    }

#pragma unroll
    for (int l = 0; l < LL; l++) {
#pragma unroll
        for (int o = 16; o > 0; o >>= 1) {
            a0[l] += __shfl_xor_sync(0xffffffffu, a0[l], o);
            a1[l] += __shfl_xor_sync(0xffffffffu, a1[l], o);
        }
    }
#pragma unroll
    for (int o = 16; o > 0; o >>= 1) {
        n0 += __shfl_xor_sync(0xffffffffu, n0, o);
        n1 += __shfl_xor_sync(0xffffffffu, n1, o);
    }

    if (lane == 0) {
        float i0 = 1.f / n0, i1 = 1.f / n1;
#pragma unroll
        for (int l = 0; l < LL; l++) {
            g_bi[l * NN + j0] = a0[l] * i0;
            g_bi[l * NN + j0 + 1] = a1[l] * i1;
        }
    }
}

// cur_out = unary + Msp @ (spatial/norm_sp) + Mbi @ bilateral(already normalized)
__global__ void combine_k(const float* __restrict__ unary, float* __restrict__ out) {
    int idx = blockIdx.x * 256 + threadIdx.x;
    int l = idx >> 12;
    int n = idx & (NN - 1);
    int z = n >> 8, y = (n >> 4) & 15, x = n & 15;
    float invs = 1.f / (g_S[z] * g_S[y] * g_S[x]);
    const float* msp = g_Msp + l * LL;
    const float* mbi = g_Mbi + l * LL;
    float ssp = 0.f, sbi = 0.f;
#pragma unroll
    for (int m = 0; m < LL; m++) {
        ssp += msp[m] * g_B[m * NN + n];   // spatial conv result lives in g_B
        sbi += mbi[m] * g_bi[m * NN + n];
    }
    out[idx] = unary[idx] + ssp * invs + sbi;
}

// Copy q into g_B as conv input staging? Not needed: conv_x reads g_q, writes g_A;
// conv_y must read conv_x's output. Fix the chain: x: g_q->g_A, y: g_A->?, z: ?->g_B.
// conv_y_k above reads g_B — wrong. Provide a corrected y-pass reading g_A:
__global__ void conv_y2_k() {
    int idx = blockIdx.x * 256 + threadIdx.x;
    int c = (idx >> 4) & 15;
    int base = idx - (c << 4);
    float a = 0.f;
#pragma unroll
    for (int t = 0; t < 16; t++) {
        int d = c - t; d = d < 0 ? -d : d;
        a += g_G[d] * g_A[base + (t << 4)];
    }
    g_B[idx] = a;
}
// z-pass: g_B -> g_B is unsafe (in-place along z). Use g_B -> g_A then combine reads g_A?
// Final chain used below: x (g_q->g_A), y2 (g_A->g_B), z2 (g_B->g_A), combine reads g_A.
__global__ void conv_z2_k() {
    int idx = blockIdx.x * 256 + threadIdx.x;
    int c = (idx >> 8) & 15;
    int base = idx - (c << 8);
    float a = 0.f;
#pragma unroll
    for (int t = 0; t < 16; t++) {
        int d = c - t; d = d < 0 ? -d : d;
        a += g_G[d] * g_B[base + (t << 8)];
    }
    g_A[idx] = a;
}
__global__ void combine2_k(const float* __restrict__ unary, float* __restrict__ out) {
    int idx = blockIdx.x * 256 + threadIdx.x;
    int l = idx >> 12;
    int n = idx & (NN - 1);
    int z = n >> 8, y = (n >> 4) & 15, x = n & 15;
    float invs = 1.f / (g_S[z] * g_S[y] * g_S[x]);
    const float* msp = g_Msp + l * LL;
    const float* mbi = g_Mbi + l * LL;
    float ssp = 0.f, sbi = 0.f;
#pragma unroll
    for (int m = 0; m < LL; m++) {
        ssp += msp[m] * g_A[m * NN + n];
        sbi += mbi[m] * g_bi[m * NN + n];
    }
    out[idx] = unary[idx] + ssp * invs + sbi;
}

// ---------------- host launch ----------------
extern "C" void kernel_launch(void* const* d_in, const int* in_sizes, int n_in,
                              void* d_out, int out_size) {
    (void)in_sizes; (void)n_in; (void)out_size;
    const float* image  = (const float*)d_in[0];
    const float* logits = (const float*)d_in[1];
    const float* wsp    = (const float*)d_in[2];
    const float* wbi    = (const float*)d_in[3];
    const float* comp   = (const float*)d_in[4];
    float* out = (float*)d_out;

    float* curbuf = nullptr;
    cudaGetSymbolAddress((void**)&curbuf, g_cur);

    init_tables_k<<<1, 32>>>();
    feat_k<<<16, 256>>>(image);
    small_mats_k<<<1, 441>>>(wsp, wbi, comp);
    buildK_k<<<dim3(32, 32), 128>>>();

    const float* cur = logits;
    for (int it = 0; it < 5; it++) {
        softmax_k<<<16, 256>>>(cur);
        conv_x_k<<<336, 256>>>();    // g_q -> g_A
        conv_y2_k<<<336, 256>>>();   // g_A -> g_B
        conv_z2_k<<<336, 256>>>();   // g_B -> g_A (spatial result)
        gemm_bi_k<<<256, 256>>>();   // g_q x g_K -> g_bi (normalized)
        float* dst = (it == 4) ? out : curbuf;
        combine2_k<<<336, 256>>>(logits, dst);
        cur = curbuf;
    }
}

// round 7
// speedup vs baseline: 1.5369x; 1.5369x over previous
#include <cuda_runtime.h>
#include <cuda_bf16.h>
#include <math.h>
#include <stdint.h>

#define NN 4096          // D*W*H = 16*16*16
#define LL 21            // labels
#define LN (LL * NN)

// ---------------- device scratch (static allocation, allowed) ----------------
__device__ __nv_bfloat16 g_Kb[16777216];   // 4096x4096 bilateral kernel, bf16 row-major (32 MB)
__device__ float         g_F[NN * 8];      // per-voxel features: f0..f5, h=-0.5*|f|^2, pad
__device__ float         g_q[LN];          // softmax output (fp32, for spatial conv)
__device__ __nv_bfloat16 g_qb[24 * NN];    // bf16 q rows 0..20, row 21 = ones, 22..23 = 0
__device__ float         g_A[LN];          // spatial conv result
__device__ float         g_P[NN * 32];     // bilateral GEMM output P[j][c] (c=21 -> normalizer)
__device__ float         g_cur[LN];        // logits between iterations
__device__ float         g_Msp[LL * LL];   // compat @ spatial_weights
__device__ float         g_Mbi[LL * LL];   // compat @ bilateral_weights
__device__ float         g_G[16];          // 1D spatial Gaussian taps
__device__ float         g_S[16];          // 1D normalizer sums

// ---------------- setup kernels ----------------
__global__ void setup_k(const float* __restrict__ wsp,
                        const float* __restrict__ wbi,
                        const float* __restrict__ comp) {
    int t = threadIdx.x;
    if (t < 16) {
        g_G[t] = expf(-0.5f * (float)(t * t));
        float s = 0.f;
        for (int u = 0; u < 16; u++) {
            int d = t - u;
            s += expf(-0.5f * (float)(d * d));
        }
        g_S[t] = s;
    }
    if (t < LL * LL) {
        int l = t / LL, m = t % LL;
        float s1 = 0.f, s2 = 0.f;
        for (int k = 0; k < LL; k++) {
            float c = comp[l * LL + k];
            s1 += c * wsp[k * LL + m];
            s2 += c * wbi[k * LL + m];
        }
        g_Msp[t] = s1;
        g_Mbi[t] = s2;
    }
}

__global__ void feat_k(const float* __restrict__ img) {
    int n = blockIdx.x * 256 + threadIdx.x;
    if (n >= NN) return;
    float z = (float)(n >> 8);
    float y = (float)((n >> 4) & 15);
    float x = (float)(n & 15);
    const float ia = 1.f / 67.f, ib = 1.f / 3.f;
    float f0 = z * ia, f1 = y * ia, f2 = x * ia;
    float f3 = img[n] * ib;
    float f4 = img[NN + n] * ib;
    float f5 = img[2 * NN + n] * ib;
    float h = -0.5f * (f0 * f0 + f1 * f1 + f2 * f2 + f3 * f3 + f4 * f4 + f5 * f5);
    float* p = g_F + n * 8;
    p[0] = f0; p[1] = f1; p[2] = f2; p[3] = f3; p[4] = f4; p[5] = f5; p[6] = h; p[7] = 0.f;
    // static qb rows: 21 = ones (normalizer column), 22..23 = 0
    g_qb[21 * NN + n] = __float2bfloat16(1.0f);
    g_qb[22 * NN + n] = __float2bfloat16(0.0f);
    g_qb[23 * NN + n] = __float2bfloat16(0.0f);
}

// ---------------- K_bi build (bf16 output) ----------------
__global__ void buildK_k() {
    int j0 = blockIdx.x * 128;
    int i0 = blockIdx.y * 128;
    int w = threadIdx.x >> 5;
    int lane = threadIdx.x & 31;
    int jb = j0 + lane * 4;

    float fj[4][7];
#pragma unroll
    for (int s = 0; s < 4; s++) {
        const float4* fp = (const float4*)(g_F + (size_t)(jb + s) * 8);
        float4 a = fp[0];
        float4 b = fp[1];
        fj[s][0] = a.x; fj[s][1] = a.y; fj[s][2] = a.z; fj[s][3] = a.w;
        fj[s][4] = b.x; fj[s][5] = b.y; fj[s][6] = b.z;
    }

    for (int ii = 0; ii < 32; ii++) {
        int i = i0 + w * 32 + ii;
        const float4* fp = (const float4*)(g_F + (size_t)i * 8);
        float4 a = fp[0];
        float4 b = fp[1];  // b.z = h_i
        float o[4];
#pragma unroll
        for (int s = 0; s < 4; s++) {
            float e = b.z + fj[s][6]
                    + a.x * fj[s][0] + a.y * fj[s][1] + a.z * fj[s][2]
                    + b.x * fj[s][4] + b.y * fj[s][5] + a.w * fj[s][3];
            o[s] = __expf(fminf(e, 0.f));
        }
        __nv_bfloat162 p0 = __floats2bfloat162_rn(o[0], o[1]);
        __nv_bfloat162 p1 = __floats2bfloat162_rn(o[2], o[3]);
        uint2 v;
        v.x = *(uint32_t*)&p0;
        v.y = *(uint32_t*)&p1;
        *(uint2*)(g_Kb + (size_t)i * NN + jb) = v;
    }
}

// ---------------- softmax + qb emit + zero P ----------------
__global__ void softmax_k(const float* __restrict__ cur) {
    int n = blockIdx.x * 256 + threadIdx.x;
    if (n >= NN) return;
    float v[LL];
    float m = -1e30f;
#pragma unroll
    for (int l = 0; l < LL; l++) {
        v[l] = cur[l * NN + n];
        m = fmaxf(m, v[l]);
    }
    float s = 0.f;
#pragma unroll
    for (int l = 0; l < LL; l++) {
        v[l] = __expf(v[l] - m);
        s += v[l];
    }
    float inv = 1.f / s;
#pragma unroll
    for (int l = 0; l < LL; l++) {
        float q = v[l] * inv;
        g_q[l * NN + n] = q;
        g_qb[l * NN + n] = __float2bfloat16(q);
    }
    // zero P row for this voxel (previous combine already consumed it)
    float4 z4 = make_float4(0.f, 0.f, 0.f, 0.f);
    float4* P4 = (float4*)(g_P + (size_t)n * 32);
#pragma unroll
    for (int k = 0; k < 8; k++) P4[k] = z4;
}

// ---------------- fused separable spatial filter (x,y,z in one kernel) ----------------
__global__ void spatial_k() {
    __shared__ float s0[4096];
    __shared__ float s1[4096];
    __shared__ float Gs[16];
    int l = blockIdx.x;
    int t = threadIdx.x;
    if (t < 16) Gs[t] = g_G[t];
    const float* src = g_q + (size_t)l * NN;
#pragma unroll
    for (int k = 0; k < 16; k++) s0[t + k * 256] = src[t + k * 256];
    __syncthreads();
#pragma unroll
    for (int k = 0; k < 16; k++) {
        int n = t + k * 256;
        int x = n & 15, b = n - x;
        float a = 0.f;
#pragma unroll
        for (int tt = 0; tt < 16; tt++) {
            int d = x - tt; d = d < 0 ? -d : d;
            a += Gs[d] * s0[b + tt];
        }
        s1[n] = a;
    }
    __syncthreads();
#pragma unroll
    for (int k = 0; k < 16; k++) {
        int n = t + k * 256;
        int y = (n >> 4) & 15, b = n - (y << 4);
        float a = 0.f;
#pragma unroll
        for (int tt = 0; tt < 16; tt++) {
            int d = y - tt; d = d < 0 ? -d : d;
            a += Gs[d] * s1[b + (tt << 4)];
        }
        s0[n] = a;
    }
    __syncthreads();
    float* dst = g_A + (size_t)l * NN;
#pragma unroll
    for (int k = 0; k < 16; k++) {
        int n = t + k * 256;
        int z = n >> 8, b = n & 255;
        float a = 0.f;
#pragma unroll
        for (int tt = 0; tt < 16; tt++) {
            int d = z - tt; d = d < 0 ? -d : d;
            a += Gs[d] * s0[b + (tt << 8)];
        }
        dst[n] = a;
    }
}

// ---------------- bilateral GEMM via mma.sync (HMMA, legal on sm_103) ----------------
// P[j, 0..23] += sum_{k in split} Kb[j,k] * qb[c,k]; col 21 = normalizer.
// Warp = 32 rows (2 m-tiles) x 24 cols (3 n-tiles). CTA = 4 warps = 128 rows.
// grid (32 j-blocks, 8 k-splits); k-range 512 = 32 ksteps of 16.
__device__ __forceinline__ void mma16816(float* c, const uint32_t* a, const uint32_t* b) {
    asm volatile(
        "mma.sync.aligned.m16n8k16.row.col.f32.bf16.bf16.f32 "
        "{%0,%1,%2,%3}, {%4,%5,%6,%7}, {%8,%9}, {%0,%1,%2,%3};"
        : "+f"(c[0]), "+f"(c[1]), "+f"(c[2]), "+f"(c[3])
        : "r"(a[0]), "r"(a[1]), "r"(a[2]), "r"(a[3]), "r"(b[0]), "r"(b[1]));
}

__global__ void __launch_bounds__(128) gemm_k() {
    int tid = threadIdx.x;
    int wid = tid >> 5, lane = tid & 31;
    int g = lane >> 2, t = lane & 3;          // fragment group / thread-in-group
    int rb = blockIdx.x * 128 + wid * 32;     // warp's first j row
    int k0 = blockIdx.y * 512;                // k-split base

    // A row pointers for 2 m-tiles (rows g and g+8 of each 16-row tile)
    const __nv_bfloat16* pa[4];
    pa[0] = g_Kb + (size_t)(rb + g) * NN;
    pa[1] = g_Kb + (size_t)(rb + g + 8) * NN;
    pa[2] = g_Kb + (size_t)(rb + 16 + g) * NN;
    pa[3] = g_Kb + (size_t)(rb + 16 + g + 8) * NN;
    // B row pointers for 3 n-tiles (row = col index n = nt*8 + g)
    const __nv_bfloat16* pb[3];
    pb[0] = g_qb + (size_t)(g) * NN;
    pb[1] = g_qb + (size_t)(8 + g) * NN;
    pb[2] = g_qb + (size_t)(16 + g) * NN;

    float acc[2][3][4];
#pragma unroll
    for (int m = 0; m < 2; m++)
#pragma unroll
        for (int n = 0; n < 3; n++)
#pragma unroll
            for (int r = 0; r < 4; r++) acc[m][n][r] = 0.f;

#pragma unroll 2
    for (int ks = 0; ks < 32; ks++) {
        int kk = k0 + ks * 16 + t * 2;
        uint32_t a0[4], a1[4], b[3][2];
        // m-tile 0
        a0[0] = *(const uint32_t*)(pa[0] + kk);
        a0[1] = *(const uint32_t*)(pa[1] + kk);
        a0[2] = *(const uint32_t*)(pa[0] + kk + 8);
        a0[3] = *(const uint32_t*)(pa[1] + kk + 8);
        // m-tile 1
        a1[0] = *(const uint32_t*)(pa[2] + kk);
        a1[1] = *(const uint32_t*)(pa[3] + kk);
        a1[2] = *(const uint32_t*)(pa[2] + kk + 8);
        a1[3] = *(const uint32_t*)(pa[3] + kk + 8);
        // B fragments
#pragma unroll
        for (int n = 0; n < 3; n++) {
            b[n][0] = *(const uint32_t*)(pb[n] + kk);
            b[n][1] = *(const uint32_t*)(pb[n] + kk + 8);
        }
#pragma unroll
        for (int n = 0; n < 3; n++) {
            mma16816(acc[0][n], a0, b[n]);
            mma16816(acc[1][n], a1, b[n]);
        }
    }

    // accumulate partials: C lane layout c0/c1 -> (row g, cols t*2, t*2+1), c2/c3 -> row g+8
#pragma unroll
    for (int m = 0; m < 2; m++) {
        int r0 = rb + m * 16 + g;
#pragma unroll
        for (int n = 0; n < 3; n++) {
            int c = n * 8 + t * 2;
            if (c < 21) {  // cols 0..21 useful; c is even so c<21 covers pair up to 20,21
                atomicAdd(g_P + (size_t)r0 * 32 + c, acc[m][n][0]);
                atomicAdd(g_P + (size_t)r0 * 32 + c + 1, acc[m][n][1]);
                atomicAdd(g_P + (size_t)(r0 + 8) * 32 + c, acc[m][n][2]);
                atomicAdd(g_P + (size_t)(r0 + 8) * 32 + c + 1, acc[m][n][3]);
            }
        }
    }
}

// ---------------- combine: unary + Msp@(spatial/norm) + Mbi@(P/Pnorm) ----------------
__global__ void combine_k(const float* __restrict__ unary, float* __restrict__ out) {
    int idx = blockIdx.x * 256 + threadIdx.x;
    int l = idx >> 12;
    int n = idx & (NN - 1);
    int z = n >> 8, y = (n >> 4) & 15, x = n & 15;
    float invs = 1.f / (g_S[z] * g_S[y] * g_S[x]);
    const float* Pn = g_P + (size_t)n * 32;
    float invb = 1.f / Pn[21];
    const float* msp = g_Msp + l * LL;
    const float* mbi = g_Mbi + l * LL;
    float ssp = 0.f, sbi = 0.f;
#pragma unroll
    for (int m = 0; m < LL; m++) {
        ssp += msp[m] * g_A[m * NN + n];
        sbi += mbi[m] * Pn[m];
    }
    out[idx] = unary[idx] + ssp * invs + sbi * invb;
}

// ---------------- host launch ----------------
extern "C" void kernel_launch(void* const* d_in, const int* in_sizes, int n_in,
                              void* d_out, int out_size) {
    (void)in_sizes; (void)n_in; (void)out_size;
    const float* image  = (const float*)d_in[0];
    const float* logits = (const float*)d_in[1];
    const float* wsp    = (const float*)d_in[2];
    const float* wbi    = (const float*)d_in[3];
    const float* comp   = (const float*)d_in[4];
    float* out = (float*)d_out;

    float* curbuf = nullptr;
    cudaGetSymbolAddress((void**)&curbuf, g_cur);

    setup_k<<<1, 441>>>(wsp, wbi, comp);
    feat_k<<<16, 256>>>(image);
    buildK_k<<<dim3(32, 32), 128>>>();

    const float* cur = logits;
    for (int it = 0; it < 5; it++) {
        softmax_k<<<16, 256>>>(cur);
        spatial_k<<<21, 256>>>();
        gemm_k<<<dim3(32, 8), 128>>>();
        float* dst = (it == 4) ? out : curbuf;
        combine_k<<<336, 256>>>(logits, dst);
        cur = curbuf;
    }
}